// round 2
// baseline (speedup 1.0000x reference)
#include <cuda_runtime.h>
#include <cstdint>

#define FULL 0xffffffffu

__device__ float g_step;

// ---------- f32x2 packed helpers (sm_103a) ----------
static __device__ __forceinline__ unsigned long long pack2(float lo, float hi) {
    unsigned long long r;
    asm("mov.b64 %0, {%1, %2};" : "=l"(r) : "f"(lo), "f"(hi));
    return r;
}
static __device__ __forceinline__ void unpack2(unsigned long long v, float& lo, float& hi) {
    asm("mov.b64 {%0, %1}, %2;" : "=f"(lo), "=f"(hi) : "l"(v));
}
static __device__ __forceinline__ unsigned long long fma2(unsigned long long a,
                                                          unsigned long long b,
                                                          unsigned long long c) {
    unsigned long long d;
    asm("fma.rn.f32x2 %0, %1, %2, %3;" : "=l"(d) : "l"(a), "l"(b), "l"(c));
    return d;
}
static __device__ __forceinline__ unsigned long long add2(unsigned long long a,
                                                          unsigned long long b) {
    unsigned long long d;
    asm("add.rn.f32x2 %0, %1, %2;" : "=l"(d) : "l"(a), "l"(b));
    return d;
}

// ---------- Kernel 1: power iteration for L = lambda_max(Sigma), step = 1/L ----------
__global__ void power_kernel(const float* __restrict__ sigma) {
    __shared__ float S[64 * 64];
    __shared__ float v[64];
    __shared__ float red[64];
    int t = threadIdx.x;  // 0..63
    for (int i = t; i < 4096; i += 64) S[i] = sigma[i];
    v[t] = 0.125f;  // unit norm
    __syncthreads();

    float u = 0.f;
    for (int it = 0; it < 600; ++it) {
        u = 0.f;
        // Sigma symmetric: u_t = sum_i S[i][t] * v[i]  (conflict-free smem reads)
        #pragma unroll 8
        for (int i = 0; i < 64; ++i) u = fmaf(S[i * 64 + t], v[i], u);
        red[t] = u * u;
        __syncthreads();
        #pragma unroll
        for (int s = 32; s > 0; s >>= 1) {
            if (t < s) red[t] += red[t + s];
            __syncthreads();
        }
        float inv = rsqrtf(red[0]);
        __syncthreads();
        v[t] = u * inv;
        __syncthreads();
    }
    // Rayleigh quotient: lambda = v . (S v), v unit-norm
    float uu = 0.f;
    #pragma unroll 8
    for (int i = 0; i < 64; ++i) uu = fmaf(S[i * 64 + t], v[i], uu);
    red[t] = uu * v[t];
    __syncthreads();
    #pragma unroll
    for (int s = 32; s > 0; s >>= 1) {
        if (t < s) red[t] += red[t + s];
        __syncthreads();
    }
    if (t == 0) g_step = 1.0f / red[0];
}

// ---------- Kernel 2: MLP -> mu ----------
__global__ void __launch_bounds__(256) mlp_kernel(
    const float* __restrict__ x,
    const float* __restrict__ W1, const float* __restrict__ b1,
    const float* __restrict__ W2, const float* __restrict__ b2,
    const float* __restrict__ W3, const float* __restrict__ b3,
    float* __restrict__ mu_out, int B)
{
    __shared__ float W1s[128 * 32];
    __shared__ float W2s[32 * 16];
    __shared__ float W3s[16 * 64];
    __shared__ float b1s[32], b2s[16], b3s[64];

    int tid = threadIdx.x;
    for (int i = tid; i < 4096; i += 256) W1s[i] = W1[i];
    for (int i = tid; i < 512;  i += 256) W2s[i] = W2[i];
    for (int i = tid; i < 1024; i += 256) W3s[i] = W3[i];
    if (tid < 32) b1s[tid] = b1[tid];
    if (tid < 16) b2s[tid] = b2[tid];
    if (tid < 64) b3s[tid] = b3[tid];
    __syncthreads();

    int lane = tid & 31;
    int row  = blockIdx.x * 8 + (tid >> 5);
    if (row >= B) return;

    // x row: 128 floats, 4 per lane
    float4 xv = reinterpret_cast<const float4*>(x + (size_t)row * 128)[lane];

    // h1[j], j = lane (H1 = 32)
    float h1 = b1s[lane];
    #pragma unroll
    for (int k = 0; k < 32; ++k) {
        float a0 = __shfl_sync(FULL, xv.x, k);
        float a1 = __shfl_sync(FULL, xv.y, k);
        float a2 = __shfl_sync(FULL, xv.z, k);
        float a3 = __shfl_sync(FULL, xv.w, k);
        int d = 4 * k;
        h1 = fmaf(a0, W1s[(d + 0) * 32 + lane], h1);
        h1 = fmaf(a1, W1s[(d + 1) * 32 + lane], h1);
        h1 = fmaf(a2, W1s[(d + 2) * 32 + lane], h1);
        h1 = fmaf(a3, W1s[(d + 3) * 32 + lane], h1);
    }
    h1 = fmaxf(h1, 0.f);

    // h2[j], j = lane & 15 (H2 = 16, duplicated on upper half-warp)
    int j = lane & 15;
    float h2 = b2s[j];
    #pragma unroll
    for (int k = 0; k < 32; ++k) {
        float hk = __shfl_sync(FULL, h1, k);
        h2 = fmaf(hk, W2s[k * 16 + j], h2);
    }
    h2 = fmaxf(h2, 0.f);

    // mu[c], c = 2*lane, 2*lane+1 (N = 64)
    float m0 = b3s[2 * lane];
    float m1 = b3s[2 * lane + 1];
    #pragma unroll
    for (int k = 0; k < 16; ++k) {
        float hk = __shfl_sync(FULL, h2, k);
        m0 = fmaf(hk, W3s[k * 64 + 2 * lane],     m0);
        m1 = fmaf(hk, W3s[k * 64 + 2 * lane + 1], m1);
    }
    reinterpret_cast<float2*>(mu_out + (size_t)row * 64)[lane] = make_float2(m0, m1);
}

// ---------- Kernel 3: FISTA (one warp per batch row) ----------
__global__ void __launch_bounds__(128) fista_kernel(
    const float* __restrict__ sigma,
    const float* __restrict__ gamma,
    float* __restrict__ out, int B)
{
    int gw   = (blockIdx.x * blockDim.x + threadIdx.x) >> 5;
    int lane = threadIdx.x & 31;
    if (gw >= B) return;

    const float gm   = __ldg(gamma);
    const float step = g_step;
    const int   c0   = 2 * lane;  // lane owns elements/columns 2l, 2l+1

    // Sigma rows c0 and c0+1, packed in pairs along i: sp[k] = (S[c][2k], S[c][2k+1])
    unsigned long long sp0[32], sp1[32];
    {
        const unsigned long long* r0 =
            reinterpret_cast<const unsigned long long*>(sigma + (size_t)c0 * 64);
        const unsigned long long* r1 =
            reinterpret_cast<const unsigned long long*>(sigma + (size_t)(c0 + 1) * 64);
        #pragma unroll
        for (int k = 0; k < 32; ++k) { sp0[k] = r0[k]; sp1[k] = r1[k]; }
    }

    // p = -gamma * mu  (mu was written to out[B*64 + ...] by mlp_kernel)
    const float2 muv =
        reinterpret_cast<const float2*>(out + (size_t)B * 64 + (size_t)gw * 64)[lane];
    const float p0 = -gm * muv.x;
    const float p1 = -gm * muv.y;

    float w0 = 1.f / 64.f, w1 = 1.f / 64.f;
    float y0 = w0, y1 = w1;
    float t = 1.f;

    #pragma unroll 1
    for (int it = 0; it < 200; ++it) {
        // grad = y @ Sigma + p (Sigma symmetric -> row dot)
        unsigned long long ypk = pack2(y0, y1);
        unsigned long long a0 = 0ull, a1 = 0ull, b0 = 0ull, b1 = 0ull;
        #pragma unroll
        for (int k = 0; k < 32; k += 2) {
            unsigned long long yk = __shfl_sync(FULL, ypk, k);
            a0 = fma2(sp0[k], yk, a0);
            a1 = fma2(sp1[k], yk, a1);
            unsigned long long yk2 = __shfl_sync(FULL, ypk, k + 1);
            b0 = fma2(sp0[k + 1], yk2, b0);
            b1 = fma2(sp1[k + 1], yk2, b1);
        }
        unsigned long long gp0 = add2(a0, b0);
        unsigned long long gp1 = add2(a1, b1);
        float g0l, g0h, g1l, g1h;
        unpack2(gp0, g0l, g0h);
        unpack2(gp1, g1l, g1h);
        float gr0 = g0l + g0h + p0;
        float gr1 = g1l + g1h + p1;

        float v0 = fmaf(-step, gr0, y0);
        float v1 = fmaf(-step, gr1, y1);

        // Simplex projection: Michelot's algorithm (exact, no sort)
        float s = v0 + v1;
        #pragma unroll
        for (int off = 16; off; off >>= 1) s += __shfl_xor_sync(FULL, s, off);
        float theta = (s - 1.f) * 0.015625f;  // /64
        int kcnt = 64;
        for (int pass = 0; pass < 64; ++pass) {
            bool act0 = v0 > theta, act1 = v1 > theta;
            float ps = (act0 ? v0 : 0.f) + (act1 ? v1 : 0.f);
            int   pc = (int)act0 + (int)act1;
            #pragma unroll
            for (int off = 16; off; off >>= 1) ps += __shfl_xor_sync(FULL, ps, off);
            int cs = (int)__reduce_add_sync(FULL, (unsigned)pc);
            if (cs == kcnt) break;   // active set unchanged -> theta final
            kcnt = cs;
            theta = (ps - 1.f) / (float)cs;
        }
        float wn0 = fmaxf(v0 - theta, 0.f);
        float wn1 = fmaxf(v1 - theta, 0.f);

        float tn = 0.5f * (1.f + sqrtf(fmaf(4.f * t, t, 1.f)));
        float cf = (t - 1.f) / tn;
        y0 = fmaf(cf, wn0 - w0, wn0);
        y1 = fmaf(cf, wn1 - w1, wn1);
        w0 = wn0; w1 = wn1; t = tn;
    }

    reinterpret_cast<float2*>(out + (size_t)gw * 64)[lane] = make_float2(w0, w1);
}

// ---------- launch ----------
extern "C" void kernel_launch(void* const* d_in, const int* in_sizes, int n_in,
                              void* d_out, int out_size) {
    const float* x     = (const float*)d_in[0];
    const float* W1    = (const float*)d_in[1];
    const float* b1    = (const float*)d_in[2];
    const float* W2    = (const float*)d_in[3];
    const float* b2    = (const float*)d_in[4];
    const float* W3    = (const float*)d_in[5];
    const float* b3    = (const float*)d_in[6];
    const float* sigma = (const float*)d_in[7];
    const float* gamma = (const float*)d_in[8];
    float* out = (float*)d_out;

    int B = in_sizes[0] / 128;  // x is [B, 128]

    power_kernel<<<1, 64>>>(sigma);
    mlp_kernel<<<(B + 7) / 8, 256>>>(x, W1, b1, W2, b2, W3, b3,
                                     out + (size_t)B * 64, B);
    fista_kernel<<<(B * 32 + 127) / 128, 128>>>(sigma, gamma, out, B);
}

// round 3
// speedup vs baseline: 1.6268x; 1.6268x over previous
#include <cuda_runtime.h>
#include <cstdint>

#define FULL 0xffffffffu
typedef unsigned long long ull;

__device__ float g_step;

// ---------- f32x2 packed helpers (sm_103a) ----------
static __device__ __forceinline__ ull pack2(float lo, float hi) {
    ull r;
    asm("mov.b64 %0, {%1, %2};" : "=l"(r) : "f"(lo), "f"(hi));
    return r;
}
static __device__ __forceinline__ void unpack2(ull v, float& lo, float& hi) {
    asm("mov.b64 {%0, %1}, %2;" : "=f"(lo), "=f"(hi) : "l"(v));
}
static __device__ __forceinline__ ull fma2(ull a, ull b, ull c) {
    ull d;
    asm("fma.rn.f32x2 %0, %1, %2, %3;" : "=l"(d) : "l"(a), "l"(b), "l"(c));
    return d;
}
static __device__ __forceinline__ ull add2(ull a, ull b) {
    ull d;
    asm("add.rn.f32x2 %0, %1, %2;" : "=l"(d) : "l"(a), "l"(b));
    return d;
}
static __device__ __forceinline__ float hadd2(ull v) {
    float lo, hi;
    unpack2(v, lo, hi);
    return lo + hi;
}

// ---------- Kernel 1: power iteration, 1 warp, Sigma in registers ----------
__global__ void __launch_bounds__(32) power_kernel(const float* __restrict__ sigma) {
    int lane = threadIdx.x;
    int c0 = 2 * lane;

    ull sp0[32], sp1[32];
    {
        const ull* r0 = reinterpret_cast<const ull*>(sigma + (size_t)c0 * 64);
        const ull* r1 = reinterpret_cast<const ull*>(sigma + (size_t)(c0 + 1) * 64);
        #pragma unroll
        for (int k = 0; k < 32; ++k) { sp0[k] = r0[k]; sp1[k] = r1[k]; }
    }

    float v0 = 0.125f, v1 = 0.125f;

    #pragma unroll 1
    for (int it = 0; it < 504; ++it) {
        ull ypk = pack2(v0, v1);
        ull a0 = 0ull, a1 = 0ull, b0 = 0ull, b1 = 0ull;
        #pragma unroll
        for (int k = 0; k < 32; k += 2) {
            ull yk = __shfl_sync(FULL, ypk, k);
            a0 = fma2(sp0[k], yk, a0);
            a1 = fma2(sp1[k], yk, a1);
            ull yk2 = __shfl_sync(FULL, ypk, k + 1);
            b0 = fma2(sp0[k + 1], yk2, b0);
            b1 = fma2(sp1[k + 1], yk2, b1);
        }
        float u0 = hadd2(add2(a0, b0));
        float u1 = hadd2(add2(a1, b1));
        if ((it & 7) == 7) {  // normalize every 8 iterations (overflow-safe: |u| <= ~5^8)
            float nn = u0 * u0 + u1 * u1;
            #pragma unroll
            for (int off = 16; off; off >>= 1) nn += __shfl_xor_sync(FULL, nn, off);
            float inv = rsqrtf(nn);
            v0 = u0 * inv; v1 = u1 * inv;
        } else {
            v0 = u0; v1 = u1;
        }
    }

    // v is unit-norm (last iter normalized). Rayleigh quotient: lam = v . (S v)
    {
        ull ypk = pack2(v0, v1);
        ull a0 = 0ull, a1 = 0ull, b0 = 0ull, b1 = 0ull;
        #pragma unroll
        for (int k = 0; k < 32; k += 2) {
            ull yk = __shfl_sync(FULL, ypk, k);
            a0 = fma2(sp0[k], yk, a0);
            a1 = fma2(sp1[k], yk, a1);
            ull yk2 = __shfl_sync(FULL, ypk, k + 1);
            b0 = fma2(sp0[k + 1], yk2, b0);
            b1 = fma2(sp1[k + 1], yk2, b1);
        }
        float u0 = hadd2(add2(a0, b0));
        float u1 = hadd2(add2(a1, b1));
        float lam = u0 * v0 + u1 * v1;
        #pragma unroll
        for (int off = 16; off; off >>= 1) lam += __shfl_xor_sync(FULL, lam, off);
        if (lane == 0) g_step = 1.0f / lam;
    }
}

// ---------- Kernel 2: MLP -> mu ----------
__global__ void __launch_bounds__(256) mlp_kernel(
    const float* __restrict__ x,
    const float* __restrict__ W1, const float* __restrict__ b1,
    const float* __restrict__ W2, const float* __restrict__ b2,
    const float* __restrict__ W3, const float* __restrict__ b3,
    float* __restrict__ mu_out, int B)
{
    __shared__ float W1s[128 * 32];
    __shared__ float W2s[32 * 16];
    __shared__ float W3s[16 * 64];
    __shared__ float b1s[32], b2s[16], b3s[64];

    int tid = threadIdx.x;
    for (int i = tid; i < 4096; i += 256) W1s[i] = W1[i];
    for (int i = tid; i < 512;  i += 256) W2s[i] = W2[i];
    for (int i = tid; i < 1024; i += 256) W3s[i] = W3[i];
    if (tid < 32) b1s[tid] = b1[tid];
    if (tid < 16) b2s[tid] = b2[tid];
    if (tid < 64) b3s[tid] = b3[tid];
    __syncthreads();

    int lane = tid & 31;
    int row  = blockIdx.x * 8 + (tid >> 5);
    if (row >= B) return;

    float4 xv = reinterpret_cast<const float4*>(x + (size_t)row * 128)[lane];

    float h1 = b1s[lane];
    #pragma unroll
    for (int k = 0; k < 32; ++k) {
        float a0 = __shfl_sync(FULL, xv.x, k);
        float a1 = __shfl_sync(FULL, xv.y, k);
        float a2 = __shfl_sync(FULL, xv.z, k);
        float a3 = __shfl_sync(FULL, xv.w, k);
        int d = 4 * k;
        h1 = fmaf(a0, W1s[(d + 0) * 32 + lane], h1);
        h1 = fmaf(a1, W1s[(d + 1) * 32 + lane], h1);
        h1 = fmaf(a2, W1s[(d + 2) * 32 + lane], h1);
        h1 = fmaf(a3, W1s[(d + 3) * 32 + lane], h1);
    }
    h1 = fmaxf(h1, 0.f);

    int j = lane & 15;
    float h2 = b2s[j];
    #pragma unroll
    for (int k = 0; k < 32; ++k) {
        float hk = __shfl_sync(FULL, h1, k);
        h2 = fmaf(hk, W2s[k * 16 + j], h2);
    }
    h2 = fmaxf(h2, 0.f);

    float m0 = b3s[2 * lane];
    float m1 = b3s[2 * lane + 1];
    #pragma unroll
    for (int k = 0; k < 16; ++k) {
        float hk = __shfl_sync(FULL, h2, k);
        m0 = fmaf(hk, W3s[k * 64 + 2 * lane],     m0);
        m1 = fmaf(hk, W3s[k * 64 + 2 * lane + 1], m1);
    }
    reinterpret_cast<float2*>(mu_out + (size_t)row * 64)[lane] = make_float2(m0, m1);
}

// ---------- Kernel 3: FISTA, 2 batch rows per warp, Sigma regs shared ----------
#define FIX    2097152.0f          /* 2^21 fixed-point scale for REDUX float sums */
#define INVFIX (1.0f / 2097152.0f)

__global__ void __launch_bounds__(128, 2) fista_kernel(
    const float* __restrict__ sigma,
    const float* __restrict__ gamma,
    float* __restrict__ out, int B)
{
    __shared__ float ybuf[2][4][2][64];   // [buf][warp][row][64]

    int warp = threadIdx.x >> 5;
    int lane = threadIdx.x & 31;
    int gw   = blockIdx.x * 4 + warp;     // warp task id (2 rows each)
    int rowA = 2 * gw;
    if (rowA >= B) return;
    int rowB = rowA + 1;

    const float gm   = __ldg(gamma);
    const float step = g_step;
    const int   c0   = 2 * lane;          // lane owns columns 2l, 2l+1

    ull sp0[32], sp1[32];
    {
        const ull* r0 = reinterpret_cast<const ull*>(sigma + (size_t)c0 * 64);
        const ull* r1 = reinterpret_cast<const ull*>(sigma + (size_t)(c0 + 1) * 64);
        #pragma unroll
        for (int k = 0; k < 32; ++k) { sp0[k] = r0[k]; sp1[k] = r1[k]; }
    }

    // p = -gamma * mu  (mu at out[B*64 + ...], written by mlp_kernel)
    float pA0, pA1, pB0, pB1;
    {
        const float2 ma = reinterpret_cast<const float2*>(out + (size_t)B * 64 + (size_t)rowA * 64)[lane];
        const float2 mb = reinterpret_cast<const float2*>(out + (size_t)B * 64 + (size_t)rowB * 64)[lane];
        pA0 = -gm * ma.x; pA1 = -gm * ma.y;
        pB0 = -gm * mb.x; pB1 = -gm * mb.y;
    }

    float wA0 = 1.f / 64.f, wA1 = wA0, wB0 = wA0, wB1 = wA0;
    float yA0 = wA0, yA1 = wA0, yB0 = wA0, yB1 = wA0;
    float t = 1.f;

    #pragma unroll 1
    for (int it = 0; it < 200; ++it) {
        int bsel = it & 1;
        // publish y (double-buffered; one warp-sync per iteration)
        *reinterpret_cast<ull*>(&ybuf[bsel][warp][0][c0]) = pack2(yA0, yA1);
        *reinterpret_cast<ull*>(&ybuf[bsel][warp][1][c0]) = pack2(yB0, yB1);
        __syncwarp();

        // grad = y @ Sigma + p  (Sigma symmetric -> row dot; broadcast LDS.128)
        const ulonglong2* YA = reinterpret_cast<const ulonglong2*>(&ybuf[bsel][warp][0][0]);
        const ulonglong2* YB = reinterpret_cast<const ulonglong2*>(&ybuf[bsel][warp][1][0]);
        ull aA0 = 0, aA1 = 0, bA0 = 0, bA1 = 0;
        ull aB0 = 0, aB1 = 0, bB0 = 0, bB1 = 0;
        #pragma unroll
        for (int q = 0; q < 16; ++q) {
            ulonglong2 ya = YA[q];
            aA0 = fma2(sp0[2 * q],     ya.x, aA0);
            aA1 = fma2(sp1[2 * q],     ya.x, aA1);
            bA0 = fma2(sp0[2 * q + 1], ya.y, bA0);
            bA1 = fma2(sp1[2 * q + 1], ya.y, bA1);
            ulonglong2 yb = YB[q];
            aB0 = fma2(sp0[2 * q],     yb.x, aB0);
            aB1 = fma2(sp1[2 * q],     yb.x, aB1);
            bB0 = fma2(sp0[2 * q + 1], yb.y, bB0);
            bB1 = fma2(sp1[2 * q + 1], yb.y, bB1);
        }
        float grA0 = hadd2(add2(aA0, bA0)) + pA0;
        float grA1 = hadd2(add2(aA1, bA1)) + pA1;
        float grB0 = hadd2(add2(aB0, bB0)) + pB0;
        float grB1 = hadd2(add2(aB1, bB1)) + pB1;

        float vA0 = fmaf(-step, grA0, yA0);
        float vA1 = fmaf(-step, grA1, yA1);
        float vB0 = fmaf(-step, grB0, yB0);
        float vB1 = fmaf(-step, grB1, yB1);

        // Simplex projection (Michelot), both rows interleaved.
        // Float sums via 2^21 fixed-point REDUX (theta error ~1e-6 << 1e-3 budget).
        int totA = __reduce_add_sync(FULL, __float2int_rn((vA0 + vA1) * FIX));
        int totB = __reduce_add_sync(FULL, __float2int_rn((vB0 + vB1) * FIX));
        float thA = ((float)totA * INVFIX - 1.f) * (1.f / 64.f);
        float thB = ((float)totB * INVFIX - 1.f) * (1.f / 64.f);
        int kA = 64, kB = 64;

        #pragma unroll 1
        for (int pass = 0; pass < 64; ++pass) {
            float psA = (vA0 > thA ? vA0 : 0.f) + (vA1 > thA ? vA1 : 0.f);
            int   pcA = (int)(vA0 > thA) + (int)(vA1 > thA);
            float psB = (vB0 > thB ? vB0 : 0.f) + (vB1 > thB ? vB1 : 0.f);
            int   pcB = (int)(vB0 > thB) + (int)(vB1 > thB);
            int sA = __reduce_add_sync(FULL, __float2int_rn(psA * FIX));
            int cA = __reduce_add_sync(FULL, pcA);
            int sB = __reduce_add_sync(FULL, __float2int_rn(psB * FIX));
            int cB = __reduce_add_sync(FULL, pcB);
            bool done = (cA == kA) & (cB == kB);
            kA = cA; kB = cB;
            thA = __fdividef((float)sA * INVFIX - 1.f, (float)cA);
            thB = __fdividef((float)sB * INVFIX - 1.f, (float)cB);
            if (done) break;   // recompute with same active set -> theta unchanged
        }

        float wnA0 = fmaxf(vA0 - thA, 0.f);
        float wnA1 = fmaxf(vA1 - thA, 0.f);
        float wnB0 = fmaxf(vB0 - thB, 0.f);
        float wnB1 = fmaxf(vB1 - thB, 0.f);

        float tn = 0.5f * (1.f + sqrtf(fmaf(4.f * t, t, 1.f)));
        float cf = __fdividef(t - 1.f, tn);
        yA0 = fmaf(cf, wnA0 - wA0, wnA0);
        yA1 = fmaf(cf, wnA1 - wA1, wnA1);
        yB0 = fmaf(cf, wnB0 - wB0, wnB0);
        yB1 = fmaf(cf, wnB1 - wB1, wnB1);
        wA0 = wnA0; wA1 = wnA1; wB0 = wnB0; wB1 = wnB1;
        t = tn;
    }

    reinterpret_cast<float2*>(out + (size_t)rowA * 64)[lane] = make_float2(wA0, wA1);
    reinterpret_cast<float2*>(out + (size_t)rowB * 64)[lane] = make_float2(wB0, wB1);
}

// ---------- launch ----------
extern "C" void kernel_launch(void* const* d_in, const int* in_sizes, int n_in,
                              void* d_out, int out_size) {
    const float* x     = (const float*)d_in[0];
    const float* W1    = (const float*)d_in[1];
    const float* b1    = (const float*)d_in[2];
    const float* W2    = (const float*)d_in[3];
    const float* b2    = (const float*)d_in[4];
    const float* W3    = (const float*)d_in[5];
    const float* b3    = (const float*)d_in[6];
    const float* sigma = (const float*)d_in[7];
    const float* gamma = (const float*)d_in[8];
    float* out = (float*)d_out;

    int B = in_sizes[0] / 128;  // x is [B, 128]

    power_kernel<<<1, 32>>>(sigma);
    mlp_kernel<<<(B + 7) / 8, 256>>>(x, W1, b1, W2, b2, W3, b3,
                                     out + (size_t)B * 64, B);
    int warps = (B + 1) / 2;
    fista_kernel<<<(warps + 3) / 4, 128>>>(sigma, gamma, out, B);
}

// round 4
// speedup vs baseline: 1.6269x; 1.0001x over previous
#include <cuda_runtime.h>
#include <cstdint>

#define FULL 0xffffffffu
typedef unsigned long long ull;

__device__ float g_step;

// ---------- f32x2 packed helpers (sm_103a) ----------
static __device__ __forceinline__ ull pack2(float lo, float hi) {
    ull r;
    asm("mov.b64 %0, {%1, %2};" : "=l"(r) : "f"(lo), "f"(hi));
    return r;
}
static __device__ __forceinline__ void unpack2(ull v, float& lo, float& hi) {
    asm("mov.b64 {%0, %1}, %2;" : "=f"(lo), "=f"(hi) : "l"(v));
}
static __device__ __forceinline__ ull fma2(ull a, ull b, ull c) {
    ull d;
    asm("fma.rn.f32x2 %0, %1, %2, %3;" : "=l"(d) : "l"(a), "l"(b), "l"(c));
    return d;
}
static __device__ __forceinline__ ull add2(ull a, ull b) {
    ull d;
    asm("add.rn.f32x2 %0, %1, %2;" : "=l"(d) : "l"(a), "l"(b));
    return d;
}
static __device__ __forceinline__ float hadd2(ull v) {
    float lo, hi;
    unpack2(v, lo, hi);
    return lo + hi;
}

// ---------- Kernel 1: power iteration, 1 warp, Sigma in registers ----------
__global__ void __launch_bounds__(32) power_kernel(const float* __restrict__ sigma) {
    int lane = threadIdx.x;
    int c0 = 2 * lane;

    ull sp0[32], sp1[32];
    {
        const ull* r0 = reinterpret_cast<const ull*>(sigma + (size_t)c0 * 64);
        const ull* r1 = reinterpret_cast<const ull*>(sigma + (size_t)(c0 + 1) * 64);
        #pragma unroll
        for (int k = 0; k < 32; ++k) { sp0[k] = r0[k]; sp1[k] = r1[k]; }
    }

    float v0 = 0.125f, v1 = 0.125f;

    #pragma unroll 1
    for (int it = 0; it < 504; ++it) {
        ull ypk = pack2(v0, v1);
        ull a0 = 0ull, a1 = 0ull, b0 = 0ull, b1 = 0ull;
        #pragma unroll
        for (int k = 0; k < 32; k += 2) {
            ull yk = __shfl_sync(FULL, ypk, k);
            a0 = fma2(sp0[k], yk, a0);
            a1 = fma2(sp1[k], yk, a1);
            ull yk2 = __shfl_sync(FULL, ypk, k + 1);
            b0 = fma2(sp0[k + 1], yk2, b0);
            b1 = fma2(sp1[k + 1], yk2, b1);
        }
        float u0 = hadd2(add2(a0, b0));
        float u1 = hadd2(add2(a1, b1));
        if ((it & 7) == 7) {  // normalize every 8 iterations (overflow-safe: |u| <= ~5^8)
            float nn = u0 * u0 + u1 * u1;
            #pragma unroll
            for (int off = 16; off; off >>= 1) nn += __shfl_xor_sync(FULL, nn, off);
            float inv = rsqrtf(nn);
            v0 = u0 * inv; v1 = u1 * inv;
        } else {
            v0 = u0; v1 = u1;
        }
    }

    // v is unit-norm (last iter normalized). Rayleigh quotient: lam = v . (S v)
    {
        ull ypk = pack2(v0, v1);
        ull a0 = 0ull, a1 = 0ull, b0 = 0ull, b1 = 0ull;
        #pragma unroll
        for (int k = 0; k < 32; k += 2) {
            ull yk = __shfl_sync(FULL, ypk, k);
            a0 = fma2(sp0[k], yk, a0);
            a1 = fma2(sp1[k], yk, a1);
            ull yk2 = __shfl_sync(FULL, ypk, k + 1);
            b0 = fma2(sp0[k + 1], yk2, b0);
            b1 = fma2(sp1[k + 1], yk2, b1);
        }
        float u0 = hadd2(add2(a0, b0));
        float u1 = hadd2(add2(a1, b1));
        float lam = u0 * v0 + u1 * v1;
        #pragma unroll
        for (int off = 16; off; off >>= 1) lam += __shfl_xor_sync(FULL, lam, off);
        if (lane == 0) g_step = 1.0f / lam;
    }
}

// ---------- Kernel 2: MLP -> mu ----------
__global__ void __launch_bounds__(256) mlp_kernel(
    const float* __restrict__ x,
    const float* __restrict__ W1, const float* __restrict__ b1,
    const float* __restrict__ W2, const float* __restrict__ b2,
    const float* __restrict__ W3, const float* __restrict__ b3,
    float* __restrict__ mu_out, int B)
{
    __shared__ float W1s[128 * 32];
    __shared__ float W2s[32 * 16];
    __shared__ float W3s[16 * 64];
    __shared__ float b1s[32], b2s[16], b3s[64];

    int tid = threadIdx.x;
    for (int i = tid; i < 4096; i += 256) W1s[i] = W1[i];
    for (int i = tid; i < 512;  i += 256) W2s[i] = W2[i];
    for (int i = tid; i < 1024; i += 256) W3s[i] = W3[i];
    if (tid < 32) b1s[tid] = b1[tid];
    if (tid < 16) b2s[tid] = b2[tid];
    if (tid < 64) b3s[tid] = b3[tid];
    __syncthreads();

    int lane = tid & 31;
    int row  = blockIdx.x * 8 + (tid >> 5);
    if (row >= B) return;

    float4 xv = reinterpret_cast<const float4*>(x + (size_t)row * 128)[lane];

    float h1 = b1s[lane];
    #pragma unroll
    for (int k = 0; k < 32; ++k) {
        float a0 = __shfl_sync(FULL, xv.x, k);
        float a1 = __shfl_sync(FULL, xv.y, k);
        float a2 = __shfl_sync(FULL, xv.z, k);
        float a3 = __shfl_sync(FULL, xv.w, k);
        int d = 4 * k;
        h1 = fmaf(a0, W1s[(d + 0) * 32 + lane], h1);
        h1 = fmaf(a1, W1s[(d + 1) * 32 + lane], h1);
        h1 = fmaf(a2, W1s[(d + 2) * 32 + lane], h1);
        h1 = fmaf(a3, W1s[(d + 3) * 32 + lane], h1);
    }
    h1 = fmaxf(h1, 0.f);

    int j = lane & 15;
    float h2 = b2s[j];
    #pragma unroll
    for (int k = 0; k < 32; ++k) {
        float hk = __shfl_sync(FULL, h1, k);
        h2 = fmaf(hk, W2s[k * 16 + j], h2);
    }
    h2 = fmaxf(h2, 0.f);

    float m0 = b3s[2 * lane];
    float m1 = b3s[2 * lane + 1];
    #pragma unroll
    for (int k = 0; k < 16; ++k) {
        float hk = __shfl_sync(FULL, h2, k);
        m0 = fmaf(hk, W3s[k * 64 + 2 * lane],     m0);
        m1 = fmaf(hk, W3s[k * 64 + 2 * lane + 1], m1);
    }
    reinterpret_cast<float2*>(mu_out + (size_t)row * 64)[lane] = make_float2(m0, m1);
}

// ---------- Kernel 3: FISTA, 2 batch rows per warp, Sigma regs shared ----------
#define FIX    2097152.0f          /* 2^21 fixed-point scale for REDUX float sums */
#define INVFIX (1.0f / 2097152.0f)

__global__ void __launch_bounds__(128, 2) fista_kernel(
    const float* __restrict__ sigma,
    const float* __restrict__ gamma,
    float* __restrict__ out, int B)
{
    __shared__ float ybuf[2][4][2][64];   // [buf][warp][row][64]

    int warp = threadIdx.x >> 5;
    int lane = threadIdx.x & 31;
    int gw   = blockIdx.x * 4 + warp;     // warp task id (2 rows each)
    int rowA = 2 * gw;
    if (rowA >= B) return;
    int rowB = rowA + 1;

    const float gm   = __ldg(gamma);
    const float step = g_step;
    const int   c0   = 2 * lane;          // lane owns columns 2l, 2l+1

    ull sp0[32], sp1[32];
    {
        const ull* r0 = reinterpret_cast<const ull*>(sigma + (size_t)c0 * 64);
        const ull* r1 = reinterpret_cast<const ull*>(sigma + (size_t)(c0 + 1) * 64);
        #pragma unroll
        for (int k = 0; k < 32; ++k) { sp0[k] = r0[k]; sp1[k] = r1[k]; }
    }

    // p = -gamma * mu  (mu at out[B*64 + ...], written by mlp_kernel)
    float pA0, pA1, pB0, pB1;
    {
        const float2 ma = reinterpret_cast<const float2*>(out + (size_t)B * 64 + (size_t)rowA * 64)[lane];
        const float2 mb = reinterpret_cast<const float2*>(out + (size_t)B * 64 + (size_t)rowB * 64)[lane];
        pA0 = -gm * ma.x; pA1 = -gm * ma.y;
        pB0 = -gm * mb.x; pB1 = -gm * mb.y;
    }

    float wA0 = 1.f / 64.f, wA1 = wA0, wB0 = wA0, wB1 = wA0;
    float yA0 = wA0, yA1 = wA0, yB0 = wA0, yB1 = wA0;
    float t = 1.f;

    #pragma unroll 1
    for (int it = 0; it < 200; ++it) {
        int bsel = it & 1;
        // publish y (double-buffered; one warp-sync per iteration)
        *reinterpret_cast<ull*>(&ybuf[bsel][warp][0][c0]) = pack2(yA0, yA1);
        *reinterpret_cast<ull*>(&ybuf[bsel][warp][1][c0]) = pack2(yB0, yB1);
        __syncwarp();

        // grad = y @ Sigma + p  (Sigma symmetric -> row dot; broadcast LDS.128)
        const ulonglong2* YA = reinterpret_cast<const ulonglong2*>(&ybuf[bsel][warp][0][0]);
        const ulonglong2* YB = reinterpret_cast<const ulonglong2*>(&ybuf[bsel][warp][1][0]);
        ull aA0 = 0, aA1 = 0, bA0 = 0, bA1 = 0;
        ull aB0 = 0, aB1 = 0, bB0 = 0, bB1 = 0;
        #pragma unroll
        for (int q = 0; q < 16; ++q) {
            ulonglong2 ya = YA[q];
            aA0 = fma2(sp0[2 * q],     ya.x, aA0);
            aA1 = fma2(sp1[2 * q],     ya.x, aA1);
            bA0 = fma2(sp0[2 * q + 1], ya.y, bA0);
            bA1 = fma2(sp1[2 * q + 1], ya.y, bA1);
            ulonglong2 yb = YB[q];
            aB0 = fma2(sp0[2 * q],     yb.x, aB0);
            aB1 = fma2(sp1[2 * q],     yb.x, aB1);
            bB0 = fma2(sp0[2 * q + 1], yb.y, bB0);
            bB1 = fma2(sp1[2 * q + 1], yb.y, bB1);
        }
        float grA0 = hadd2(add2(aA0, bA0)) + pA0;
        float grA1 = hadd2(add2(aA1, bA1)) + pA1;
        float grB0 = hadd2(add2(aB0, bB0)) + pB0;
        float grB1 = hadd2(add2(aB1, bB1)) + pB1;

        float vA0 = fmaf(-step, grA0, yA0);
        float vA1 = fmaf(-step, grA1, yA1);
        float vB0 = fmaf(-step, grB0, yB0);
        float vB1 = fmaf(-step, grB1, yB1);

        // Simplex projection (Michelot), both rows interleaved.
        // Float sums via 2^21 fixed-point REDUX (theta error ~1e-6 << 1e-3 budget).
        int totA = __reduce_add_sync(FULL, __float2int_rn((vA0 + vA1) * FIX));
        int totB = __reduce_add_sync(FULL, __float2int_rn((vB0 + vB1) * FIX));
        float thA = ((float)totA * INVFIX - 1.f) * (1.f / 64.f);
        float thB = ((float)totB * INVFIX - 1.f) * (1.f / 64.f);
        int kA = 64, kB = 64;

        #pragma unroll 1
        for (int pass = 0; pass < 64; ++pass) {
            float psA = (vA0 > thA ? vA0 : 0.f) + (vA1 > thA ? vA1 : 0.f);
            int   pcA = (int)(vA0 > thA) + (int)(vA1 > thA);
            float psB = (vB0 > thB ? vB0 : 0.f) + (vB1 > thB ? vB1 : 0.f);
            int   pcB = (int)(vB0 > thB) + (int)(vB1 > thB);
            int sA = __reduce_add_sync(FULL, __float2int_rn(psA * FIX));
            int cA = __reduce_add_sync(FULL, pcA);
            int sB = __reduce_add_sync(FULL, __float2int_rn(psB * FIX));
            int cB = __reduce_add_sync(FULL, pcB);
            bool done = (cA == kA) & (cB == kB);
            kA = cA; kB = cB;
            thA = __fdividef((float)sA * INVFIX - 1.f, (float)cA);
            thB = __fdividef((float)sB * INVFIX - 1.f, (float)cB);
            if (done) break;   // recompute with same active set -> theta unchanged
        }

        float wnA0 = fmaxf(vA0 - thA, 0.f);
        float wnA1 = fmaxf(vA1 - thA, 0.f);
        float wnB0 = fmaxf(vB0 - thB, 0.f);
        float wnB1 = fmaxf(vB1 - thB, 0.f);

        float tn = 0.5f * (1.f + sqrtf(fmaf(4.f * t, t, 1.f)));
        float cf = __fdividef(t - 1.f, tn);
        yA0 = fmaf(cf, wnA0 - wA0, wnA0);
        yA1 = fmaf(cf, wnA1 - wA1, wnA1);
        yB0 = fmaf(cf, wnB0 - wB0, wnB0);
        yB1 = fmaf(cf, wnB1 - wB1, wnB1);
        wA0 = wnA0; wA1 = wnA1; wB0 = wnB0; wB1 = wnB1;
        t = tn;
    }

    reinterpret_cast<float2*>(out + (size_t)rowA * 64)[lane] = make_float2(wA0, wA1);
    reinterpret_cast<float2*>(out + (size_t)rowB * 64)[lane] = make_float2(wB0, wB1);
}

// ---------- launch ----------
extern "C" void kernel_launch(void* const* d_in, const int* in_sizes, int n_in,
                              void* d_out, int out_size) {
    const float* x     = (const float*)d_in[0];
    const float* W1    = (const float*)d_in[1];
    const float* b1    = (const float*)d_in[2];
    const float* W2    = (const float*)d_in[3];
    const float* b2    = (const float*)d_in[4];
    const float* W3    = (const float*)d_in[5];
    const float* b3    = (const float*)d_in[6];
    const float* sigma = (const float*)d_in[7];
    const float* gamma = (const float*)d_in[8];
    float* out = (float*)d_out;

    int B = in_sizes[0] / 128;  // x is [B, 128]

    power_kernel<<<1, 32>>>(sigma);
    mlp_kernel<<<(B + 7) / 8, 256>>>(x, W1, b1, W2, b2, W3, b3,
                                     out + (size_t)B * 64, B);
    int warps = (B + 1) / 2;
    fista_kernel<<<(warps + 3) / 4, 128>>>(sigma, gamma, out, B);
}

// round 9
// speedup vs baseline: 2.4825x; 1.5259x over previous
#include <cuda_runtime.h>
#include <cstdint>

#define FULL 0xffffffffu
typedef unsigned long long ull;

__device__ float g_step;

// ---------- f32x2 packed helpers (sm_103a) ----------
static __device__ __forceinline__ ull pack2(float lo, float hi) {
    ull r;
    asm("mov.b64 %0, {%1, %2};" : "=l"(r) : "f"(lo), "f"(hi));
    return r;
}
static __device__ __forceinline__ void unpack2(ull v, float& lo, float& hi) {
    asm("mov.b64 {%0, %1}, %2;" : "=f"(lo), "=f"(hi) : "l"(v));
}
static __device__ __forceinline__ ull fma2(ull a, ull b, ull c) {
    ull d;
    asm("fma.rn.f32x2 %0, %1, %2, %3;" : "=l"(d) : "l"(a), "l"(b), "l"(c));
    return d;
}
static __device__ __forceinline__ ull add2(ull a, ull b) {
    ull d;
    asm("add.rn.f32x2 %0, %1, %2;" : "=l"(d) : "l"(a), "l"(b));
    return d;
}
static __device__ __forceinline__ float hadd2(ull v) {
    float lo, hi;
    unpack2(v, lo, hi);
    return lo + hi;
}

// ---------- Kernel 1: power iteration, 1 warp, Sigma in regs, y via LDS bcast ----------
__global__ void __launch_bounds__(32) power_kernel(const float* __restrict__ sigma) {
    __shared__ float vbuf[2][64];
    int lane = threadIdx.x;
    int c0 = 2 * lane;

    ull sp0[32], sp1[32];
    {
        const ull* r0 = reinterpret_cast<const ull*>(sigma + (size_t)c0 * 64);
        const ull* r1 = reinterpret_cast<const ull*>(sigma + (size_t)(c0 + 1) * 64);
        #pragma unroll
        for (int k = 0; k < 32; ++k) { sp0[k] = r0[k]; sp1[k] = r1[k]; }
    }

    float v0 = 0.125f, v1 = 0.125f;

    #pragma unroll 1
    for (int it = 0; it < 505; ++it) {
        int bsel = it & 1;
        *reinterpret_cast<ull*>(&vbuf[bsel][c0]) = pack2(v0, v1);
        __syncwarp();
        const ulonglong2* Y = reinterpret_cast<const ulonglong2*>(&vbuf[bsel][0]);
        ull a0 = 0ull, a1 = 0ull, b0 = 0ull, b1 = 0ull;
        #pragma unroll
        for (int q = 0; q < 16; ++q) {
            ulonglong2 yq = Y[q];
            a0 = fma2(sp0[2 * q],     yq.x, a0);
            a1 = fma2(sp1[2 * q],     yq.x, a1);
            b0 = fma2(sp0[2 * q + 1], yq.y, b0);
            b1 = fma2(sp1[2 * q + 1], yq.y, b1);
        }
        float u0 = hadd2(add2(a0, b0));
        float u1 = hadd2(add2(a1, b1));
        if (it == 504) {
            // Scale-invariant Rayleigh quotient: lam = (v.Sv)/(v.v).
            // (R5 bug: assumed v unit-norm here, but last normalize was it=495.)
            float num = u0 * v0 + u1 * v1;
            float den = v0 * v0 + v1 * v1;
            #pragma unroll
            for (int off = 16; off; off >>= 1) {
                num += __shfl_xor_sync(FULL, num, off);
                den += __shfl_xor_sync(FULL, den, off);
            }
            if (lane == 0) g_step = den / num;   // 1/lambda_max
            return;
        }
        if ((it & 15) == 15) {  // normalize every 16 iters (4^16 growth fits fp32)
            float nn = u0 * u0 + u1 * u1;
            #pragma unroll
            for (int off = 16; off; off >>= 1) nn += __shfl_xor_sync(FULL, nn, off);
            float inv = rsqrtf(nn);
            v0 = u0 * inv; v1 = u1 * inv;
        } else {
            v0 = u0; v1 = u1;
        }
    }
}

// ---------- Kernel 2: MLP -> mu ----------
__global__ void __launch_bounds__(256) mlp_kernel(
    const float* __restrict__ x,
    const float* __restrict__ W1, const float* __restrict__ b1,
    const float* __restrict__ W2, const float* __restrict__ b2,
    const float* __restrict__ W3, const float* __restrict__ b3,
    float* __restrict__ mu_out, int B)
{
    __shared__ float W1s[128 * 32];
    __shared__ float W2s[32 * 16];
    __shared__ float W3s[16 * 64];
    __shared__ float b1s[32], b2s[16], b3s[64];

    int tid = threadIdx.x;
    for (int i = tid; i < 4096; i += 256) W1s[i] = W1[i];
    for (int i = tid; i < 512;  i += 256) W2s[i] = W2[i];
    for (int i = tid; i < 1024; i += 256) W3s[i] = W3[i];
    if (tid < 32) b1s[tid] = b1[tid];
    if (tid < 16) b2s[tid] = b2[tid];
    if (tid < 64) b3s[tid] = b3[tid];
    __syncthreads();

    int lane = tid & 31;
    int row  = blockIdx.x * 8 + (tid >> 5);
    if (row >= B) return;

    float4 xv = reinterpret_cast<const float4*>(x + (size_t)row * 128)[lane];

    float h1 = b1s[lane];
    #pragma unroll
    for (int k = 0; k < 32; ++k) {
        float a0 = __shfl_sync(FULL, xv.x, k);
        float a1 = __shfl_sync(FULL, xv.y, k);
        float a2 = __shfl_sync(FULL, xv.z, k);
        float a3 = __shfl_sync(FULL, xv.w, k);
        int d = 4 * k;
        h1 = fmaf(a0, W1s[(d + 0) * 32 + lane], h1);
        h1 = fmaf(a1, W1s[(d + 1) * 32 + lane], h1);
        h1 = fmaf(a2, W1s[(d + 2) * 32 + lane], h1);
        h1 = fmaf(a3, W1s[(d + 3) * 32 + lane], h1);
    }
    h1 = fmaxf(h1, 0.f);

    int j = lane & 15;
    float h2 = b2s[j];
    #pragma unroll
    for (int k = 0; k < 32; ++k) {
        float hk = __shfl_sync(FULL, h1, k);
        h2 = fmaf(hk, W2s[k * 16 + j], h2);
    }
    h2 = fmaxf(h2, 0.f);

    float m0 = b3s[2 * lane];
    float m1 = b3s[2 * lane + 1];
    #pragma unroll
    for (int k = 0; k < 16; ++k) {
        float hk = __shfl_sync(FULL, h2, k);
        m0 = fmaf(hk, W3s[k * 64 + 2 * lane],     m0);
        m1 = fmaf(hk, W3s[k * 64 + 2 * lane + 1], m1);
    }
    reinterpret_cast<float2*>(mu_out + (size_t)row * 64)[lane] = make_float2(m0, m1);
}

// ---------- Kernel 3: FISTA, 4 batch rows per warp ----------
#define FIX    2097152.0f          /* 2^21 fixed-point scale for REDUX float sums */
#define INVFIX (1.0f / 2097152.0f)
#define NROW 4

__global__ void __launch_bounds__(128, 2) fista_kernel(
    const float* __restrict__ sigma,
    const float* __restrict__ gamma,
    float* __restrict__ out, int B)
{
    __shared__ float ybuf[2][4][NROW][64];   // [buf][warp][row][64]

    int warp = threadIdx.x >> 5;
    int lane = threadIdx.x & 31;
    int gw   = blockIdx.x * 4 + warp;        // warp task id (NROW rows each)
    int row0 = NROW * gw;
    if (row0 >= B) return;

    const float gm   = __ldg(gamma);
    const float step = g_step;
    const int   c0   = 2 * lane;             // lane owns columns 2l, 2l+1

    ull sp0[32], sp1[32];
    {
        const ull* r0 = reinterpret_cast<const ull*>(sigma + (size_t)c0 * 64);
        const ull* r1 = reinterpret_cast<const ull*>(sigma + (size_t)(c0 + 1) * 64);
        #pragma unroll
        for (int k = 0; k < 32; ++k) { sp0[k] = r0[k]; sp1[k] = r1[k]; }
    }

    // p = -gamma * mu  (mu at out[B*64 + ...], written by mlp_kernel)
    float p0[NROW], p1[NROW];
    #pragma unroll
    for (int r = 0; r < NROW; ++r) {
        const float2 m = reinterpret_cast<const float2*>(
            out + (size_t)B * 64 + (size_t)(row0 + r) * 64)[lane];
        p0[r] = -gm * m.x; p1[r] = -gm * m.y;
    }

    float w0[NROW], w1[NROW], y0[NROW], y1[NROW], th[NROW];
    #pragma unroll
    for (int r = 0; r < NROW; ++r) {
        w0[r] = 1.f / 64.f; w1[r] = 1.f / 64.f;
        y0[r] = w0[r];      y1[r] = w1[r];
        th[r] = -1e30f;     // warm-start theta; -inf => cold start on iter 0
    }
    float t = 1.f;
    int cc = 0;

    #pragma unroll 1
    for (int it = 0; it < 200; ++it) {
        int bsel = it & 1;
        #pragma unroll
        for (int r = 0; r < NROW; ++r)
            *reinterpret_cast<ull*>(&ybuf[bsel][warp][r][c0]) = pack2(y0[r], y1[r]);
        __syncwarp();

        // grad = y @ Sigma + p  (Sigma symmetric; broadcast LDS.128 reads)
        ull a0[NROW], a1[NROW];
        #pragma unroll
        for (int r = 0; r < NROW; ++r) { a0[r] = 0ull; a1[r] = 0ull; }
        #pragma unroll
        for (int q = 0; q < 16; ++q) {
            #pragma unroll
            for (int r = 0; r < NROW; ++r) {
                ulonglong2 yq = reinterpret_cast<const ulonglong2*>(&ybuf[bsel][warp][r][0])[q];
                a0[r] = fma2(sp0[2 * q],     yq.x, a0[r]);
                a1[r] = fma2(sp1[2 * q],     yq.x, a1[r]);
                a0[r] = fma2(sp0[2 * q + 1], yq.y, a0[r]);
                a1[r] = fma2(sp1[2 * q + 1], yq.y, a1[r]);
            }
        }

        float v0[NROW], v1[NROW];
        #pragma unroll
        for (int r = 0; r < NROW; ++r) {
            float gr0 = hadd2(a0[r]) + p0[r];
            float gr1 = hadd2(a1[r]) + p1[r];
            v0[r] = fmaf(-step, gr0, y0[r]);
            v1[r] = fmaf(-step, gr1, y1[r]);
        }

        // Simplex projection: warm-started Newton on g(th)=sum(max(v-th,0))-1.
        // Any Newton step lands <= th*, then monotone increase, exact finite stop.
        // Float sums via 2^21 fixed-point REDUX (theta err ~1e-6 << 1e-3 budget).
        int kc[NROW];
        #pragma unroll
        for (int r = 0; r < NROW; ++r) kc[r] = -1;

        #pragma unroll 1
        for (int pass = 0; pass < 64; ++pass) {
            int s[NROW], c[NROW];
            #pragma unroll
            for (int r = 0; r < NROW; ++r) {
                bool g0 = v0[r] > th[r], g1 = v1[r] > th[r];
                float ps = (g0 ? v0[r] : 0.f) + (g1 ? v1[r] : 0.f);
                int   pc = (int)g0 + (int)g1;
                s[r] = __reduce_add_sync(FULL, __float2int_rn(ps * FIX));
                c[r] = __reduce_add_sync(FULL, pc);
            }
            bool done = true;
            #pragma unroll
            for (int r = 0; r < NROW; ++r) {
                done &= (c[r] == kc[r]);
                kc[r] = c[r];
                // c==0 only possible on pass 0 (warm theta too high): cold restart
                th[r] = (c[r] > 0)
                    ? __fdividef((float)s[r] * INVFIX - 1.f, (float)c[r])
                    : -1e30f;
            }
            if (done) break;  // same active set twice => consistent fixed point
        }

        float mxchg = 0.f;
        float wn0[NROW], wn1[NROW];
        #pragma unroll
        for (int r = 0; r < NROW; ++r) {
            wn0[r] = fmaxf(v0[r] - th[r], 0.f);
            wn1[r] = fmaxf(v1[r] - th[r], 0.f);
            mxchg = fmaxf(mxchg, fmaxf(fabsf(wn0[r] - w0[r]), fabsf(wn1[r] - w1[r])));
        }

        float tn = 0.5f * (1.f + sqrtf(fmaf(4.f * t, t, 1.f)));
        float cf = __fdividef(t - 1.f, tn);
        #pragma unroll
        for (int r = 0; r < NROW; ++r) {
            y0[r] = fmaf(cf, wn0[r] - w0[r], wn0[r]);
            y1[r] = fmaf(cf, wn1[r] - w1[r], wn1[r]);
            w0[r] = wn0[r]; w1[r] = wn1[r];
        }
        t = tn;

        // Early exit: w frozen (<5e-8) across whole warp for 2 consecutive iters.
        // Remaining reference drift decays geometrically => ~1e-6 abs << 1e-3.
        if (__all_sync(FULL, mxchg < 5e-8f)) {
            if (++cc >= 2) break;
        } else {
            cc = 0;
        }
    }

    #pragma unroll
    for (int r = 0; r < NROW; ++r)
        reinterpret_cast<float2*>(out + (size_t)(row0 + r) * 64)[lane] =
            make_float2(w0[r], w1[r]);
}

// ---------- launch ----------
extern "C" void kernel_launch(void* const* d_in, const int* in_sizes, int n_in,
                              void* d_out, int out_size) {
    const float* x     = (const float*)d_in[0];
    const float* W1    = (const float*)d_in[1];
    const float* b1    = (const float*)d_in[2];
    const float* W2    = (const float*)d_in[3];
    const float* b2    = (const float*)d_in[4];
    const float* W3    = (const float*)d_in[5];
    const float* b3    = (const float*)d_in[6];
    const float* sigma = (const float*)d_in[7];
    const float* gamma = (const float*)d_in[8];
    float* out = (float*)d_out;

    int B = in_sizes[0] / 128;  // x is [B, 128]

    power_kernel<<<1, 32>>>(sigma);
    mlp_kernel<<<(B + 7) / 8, 256>>>(x, W1, b1, W2, b2, W3, b3,
                                     out + (size_t)B * 64, B);
    int warps = (B + NROW - 1) / NROW;
    fista_kernel<<<(warps + 3) / 4, 128>>>(sigma, gamma, out, B);
}

// round 10
// speedup vs baseline: 3.0563x; 1.2312x over previous
#include <cuda_runtime.h>
#include <cstdint>

#define FULL 0xffffffffu
typedef unsigned long long ull;

__device__ float g_step;

// ---------- f32x2 packed helpers (sm_103a) ----------
static __device__ __forceinline__ ull pack2(float lo, float hi) {
    ull r;
    asm("mov.b64 %0, {%1, %2};" : "=l"(r) : "f"(lo), "f"(hi));
    return r;
}
static __device__ __forceinline__ void unpack2(ull v, float& lo, float& hi) {
    asm("mov.b64 {%0, %1}, %2;" : "=f"(lo), "=f"(hi) : "l"(v));
}
static __device__ __forceinline__ ull fma2(ull a, ull b, ull c) {
    ull d;
    asm("fma.rn.f32x2 %0, %1, %2, %3;" : "=l"(d) : "l"(a), "l"(b), "l"(c));
    return d;
}
static __device__ __forceinline__ ull add2(ull a, ull b) {
    ull d;
    asm("add.rn.f32x2 %0, %1, %2;" : "=l"(d) : "l"(a), "l"(b));
    return d;
}
static __device__ __forceinline__ float hadd2(ull v) {
    float lo, hi;
    unpack2(v, lo, hi);
    return lo + hi;
}

// ---------- power iteration body (1 warp): step = 1/(1.02 * lambda_max) ----------
static __device__ void power_body(const float* __restrict__ sigma, int lane) {
    __shared__ float vbuf[2][64];
    int c0 = 2 * lane;

    ull sp0[32], sp1[32];
    {
        const ull* r0 = reinterpret_cast<const ull*>(sigma + (size_t)c0 * 64);
        const ull* r1 = reinterpret_cast<const ull*>(sigma + (size_t)(c0 + 1) * 64);
        #pragma unroll
        for (int k = 0; k < 32; ++k) { sp0[k] = r0[k]; sp1[k] = r1[k]; }
    }

    float v0 = 0.125f, v1 = 0.125f;

    #pragma unroll 1
    for (int it = 0; it < 161; ++it) {
        int bsel = it & 1;
        *reinterpret_cast<ull*>(&vbuf[bsel][c0]) = pack2(v0, v1);
        __syncwarp();
        const ulonglong2* Y = reinterpret_cast<const ulonglong2*>(&vbuf[bsel][0]);
        ull a0 = 0ull, a1 = 0ull, b0 = 0ull, b1 = 0ull;
        #pragma unroll
        for (int q = 0; q < 16; ++q) {
            ulonglong2 yq = Y[q];
            a0 = fma2(sp0[2 * q],     yq.x, a0);
            a1 = fma2(sp1[2 * q],     yq.x, a1);
            b0 = fma2(sp0[2 * q + 1], yq.y, b0);
            b1 = fma2(sp1[2 * q + 1], yq.y, b1);
        }
        float u0 = hadd2(add2(a0, b0));
        float u1 = hadd2(add2(a1, b1));
        if (it == 160) {
            // Scale-invariant Rayleigh quotient: lam = (v.Sv)/(v.v)
            float num = u0 * v0 + u1 * v1;
            float den = v0 * v0 + v1 * v1;
            #pragma unroll
            for (int off = 16; off; off >>= 1) {
                num += __shfl_xor_sync(FULL, num, off);
                den += __shfl_xor_sync(FULL, den, off);
            }
            // 2% deflation: guards against slight lambda underestimate (fewer
            // power iters); converged FISTA fixed point is step-independent.
            if (lane == 0) g_step = den / (1.02f * num);
            return;
        }
        if ((it & 15) == 15) {  // normalize every 16 iters (4^16 growth fits fp32)
            float nn = u0 * u0 + u1 * u1;
            #pragma unroll
            for (int off = 16; off; off >>= 1) nn += __shfl_xor_sync(FULL, nn, off);
            float inv = rsqrtf(nn);
            v0 = u0 * inv; v1 = u1 * inv;
        } else {
            v0 = u0; v1 = u1;
        }
    }
}

// ---------- Kernel 1: MLP -> mu, with power iteration riding in the last block ----------
__global__ void __launch_bounds__(256) prep_kernel(
    const float* __restrict__ x,
    const float* __restrict__ W1, const float* __restrict__ b1,
    const float* __restrict__ W2, const float* __restrict__ b2,
    const float* __restrict__ W3, const float* __restrict__ b3,
    const float* __restrict__ sigma,
    float* __restrict__ mu_out, int B)
{
    if (blockIdx.x == gridDim.x - 1) {
        // power block: warp 0 only (independent of MLP, overlaps with it)
        if (threadIdx.x < 32) power_body(sigma, threadIdx.x);
        return;
    }

    __shared__ float W1s[128 * 32];
    __shared__ float W2s[32 * 16];
    __shared__ float W3s[16 * 64];
    __shared__ float b1s[32], b2s[16], b3s[64];

    int tid = threadIdx.x;
    for (int i = tid; i < 4096; i += 256) W1s[i] = W1[i];
    for (int i = tid; i < 512;  i += 256) W2s[i] = W2[i];
    for (int i = tid; i < 1024; i += 256) W3s[i] = W3[i];
    if (tid < 32) b1s[tid] = b1[tid];
    if (tid < 16) b2s[tid] = b2[tid];
    if (tid < 64) b3s[tid] = b3[tid];
    __syncthreads();

    int lane = tid & 31;
    int row  = blockIdx.x * 8 + (tid >> 5);
    if (row >= B) return;

    float4 xv = reinterpret_cast<const float4*>(x + (size_t)row * 128)[lane];

    float h1 = b1s[lane];
    #pragma unroll
    for (int k = 0; k < 32; ++k) {
        float a0 = __shfl_sync(FULL, xv.x, k);
        float a1 = __shfl_sync(FULL, xv.y, k);
        float a2 = __shfl_sync(FULL, xv.z, k);
        float a3 = __shfl_sync(FULL, xv.w, k);
        int d = 4 * k;
        h1 = fmaf(a0, W1s[(d + 0) * 32 + lane], h1);
        h1 = fmaf(a1, W1s[(d + 1) * 32 + lane], h1);
        h1 = fmaf(a2, W1s[(d + 2) * 32 + lane], h1);
        h1 = fmaf(a3, W1s[(d + 3) * 32 + lane], h1);
    }
    h1 = fmaxf(h1, 0.f);

    int j = lane & 15;
    float h2 = b2s[j];
    #pragma unroll
    for (int k = 0; k < 32; ++k) {
        float hk = __shfl_sync(FULL, h1, k);
        h2 = fmaf(hk, W2s[k * 16 + j], h2);
    }
    h2 = fmaxf(h2, 0.f);

    float m0 = b3s[2 * lane];
    float m1 = b3s[2 * lane + 1];
    #pragma unroll
    for (int k = 0; k < 16; ++k) {
        float hk = __shfl_sync(FULL, h2, k);
        m0 = fmaf(hk, W3s[k * 64 + 2 * lane],     m0);
        m1 = fmaf(hk, W3s[k * 64 + 2 * lane + 1], m1);
    }
    reinterpret_cast<float2*>(mu_out + (size_t)row * 64)[lane] = make_float2(m0, m1);
}

// ---------- Kernel 2: FISTA with periodic restart, 4 batch rows per warp ----------
#define FIX    2097152.0f          /* 2^21 fixed-point scale for REDUX float sums */
#define INVFIX (1.0f / 2097152.0f)
#define NROW 4
#define RESTART 50                 /* momentum reset period (kills FISTA ripple) */

__global__ void __launch_bounds__(128, 2) fista_kernel(
    const float* __restrict__ sigma,
    const float* __restrict__ gamma,
    float* __restrict__ out, int B)
{
    __shared__ float ybuf[2][4][NROW][64];   // [buf][warp][row][64]

    int warp = threadIdx.x >> 5;
    int lane = threadIdx.x & 31;
    int gw   = blockIdx.x * 4 + warp;        // warp task id (NROW rows each)
    int row0 = NROW * gw;
    if (row0 >= B) return;

    const float gm   = __ldg(gamma);
    const float step = g_step;
    const int   c0   = 2 * lane;             // lane owns columns 2l, 2l+1

    ull sp0[32], sp1[32];
    {
        const ull* r0 = reinterpret_cast<const ull*>(sigma + (size_t)c0 * 64);
        const ull* r1 = reinterpret_cast<const ull*>(sigma + (size_t)(c0 + 1) * 64);
        #pragma unroll
        for (int k = 0; k < 32; ++k) { sp0[k] = r0[k]; sp1[k] = r1[k]; }
    }

    // p = -gamma * mu  (mu at out[B*64 + ...], written by prep_kernel)
    float p0[NROW], p1[NROW];
    #pragma unroll
    for (int r = 0; r < NROW; ++r) {
        const float2 m = reinterpret_cast<const float2*>(
            out + (size_t)B * 64 + (size_t)(row0 + r) * 64)[lane];
        p0[r] = -gm * m.x; p1[r] = -gm * m.y;
    }

    float w0[NROW], w1[NROW], y0[NROW], y1[NROW], th[NROW];
    #pragma unroll
    for (int r = 0; r < NROW; ++r) {
        w0[r] = 1.f / 64.f; w1[r] = 1.f / 64.f;
        y0[r] = w0[r];      y1[r] = w1[r];
        th[r] = -1e30f;     // warm-start theta; -inf => cold start on iter 0
    }
    float t = 1.f;
    int cc = 0, rsc = 0;

    #pragma unroll 1
    for (int it = 0; it < 200; ++it) {
        int bsel = it & 1;
        #pragma unroll
        for (int r = 0; r < NROW; ++r)
            *reinterpret_cast<ull*>(&ybuf[bsel][warp][r][c0]) = pack2(y0[r], y1[r]);
        __syncwarp();

        // grad = y @ Sigma + p  (Sigma symmetric; broadcast LDS.128 reads)
        ull a0[NROW], a1[NROW];
        #pragma unroll
        for (int r = 0; r < NROW; ++r) { a0[r] = 0ull; a1[r] = 0ull; }
        #pragma unroll
        for (int q = 0; q < 16; ++q) {
            #pragma unroll
            for (int r = 0; r < NROW; ++r) {
                ulonglong2 yq = reinterpret_cast<const ulonglong2*>(&ybuf[bsel][warp][r][0])[q];
                a0[r] = fma2(sp0[2 * q],     yq.x, a0[r]);
                a1[r] = fma2(sp1[2 * q],     yq.x, a1[r]);
                a0[r] = fma2(sp0[2 * q + 1], yq.y, a0[r]);
                a1[r] = fma2(sp1[2 * q + 1], yq.y, a1[r]);
            }
        }

        float v0[NROW], v1[NROW];
        #pragma unroll
        for (int r = 0; r < NROW; ++r) {
            float gr0 = hadd2(a0[r]) + p0[r];
            float gr1 = hadd2(a1[r]) + p1[r];
            v0[r] = fmaf(-step, gr0, y0[r]);
            v1[r] = fmaf(-step, gr1, y1[r]);
        }

        // Simplex projection: warm-started Newton on g(th)=sum(max(v-th,0))-1.
        // First step lands <= th*, then monotone increase, exact finite stop.
        // Float sums via 2^21 fixed-point REDUX (theta err ~1e-6 << 1e-3 budget).
        int kc[NROW];
        #pragma unroll
        for (int r = 0; r < NROW; ++r) kc[r] = -1;

        #pragma unroll 1
        for (int pass = 0; pass < 64; ++pass) {
            int s[NROW], c[NROW];
            #pragma unroll
            for (int r = 0; r < NROW; ++r) {
                bool g0 = v0[r] > th[r], g1 = v1[r] > th[r];
                float ps = (g0 ? v0[r] : 0.f) + (g1 ? v1[r] : 0.f);
                int   pc = (int)g0 + (int)g1;
                s[r] = __reduce_add_sync(FULL, __float2int_rn(ps * FIX));
                c[r] = __reduce_add_sync(FULL, pc);
            }
            bool done = true;
            #pragma unroll
            for (int r = 0; r < NROW; ++r) {
                done &= (c[r] == kc[r]);
                kc[r] = c[r];
                // c==0 only possible on pass 0 (warm theta too high): cold restart
                th[r] = (c[r] > 0)
                    ? __fdividef((float)s[r] * INVFIX - 1.f, (float)c[r])
                    : -1e30f;
            }
            if (done) break;  // same active set twice => consistent fixed point
        }

        float mxchg = 0.f;
        float wn0[NROW], wn1[NROW];
        #pragma unroll
        for (int r = 0; r < NROW; ++r) {
            wn0[r] = fmaxf(v0[r] - th[r], 0.f);
            wn1[r] = fmaxf(v1[r] - th[r], 0.f);
            mxchg = fmaxf(mxchg, fmaxf(fabsf(wn0[r] - w0[r]), fabsf(wn1[r] - w1[r])));
        }

        // Periodic restart: dump momentum so w converges monotonically
        // (same fixed point; enables the early exit below to actually fire).
        bool restart = (++rsc == RESTART);
        if (restart) rsc = 0;
        float tn = restart ? 1.f : 0.5f * (1.f + sqrtf(fmaf(4.f * t, t, 1.f)));
        float cf = restart ? 0.f : __fdividef(t - 1.f, tn);
        #pragma unroll
        for (int r = 0; r < NROW; ++r) {
            y0[r] = fmaf(cf, wn0[r] - w0[r], wn0[r]);
            y1[r] = fmaf(cf, wn1[r] - w1[r], wn1[r]);
            w0[r] = wn0[r]; w1[r] = wn1[r];
        }
        t = tn;

        // Early exit: w frozen (<1e-7) across whole warp for 2 consecutive iters.
        if (__all_sync(FULL, mxchg < 1e-7f)) {
            if (++cc >= 2) break;
        } else {
            cc = 0;
        }
    }

    #pragma unroll
    for (int r = 0; r < NROW; ++r)
        reinterpret_cast<float2*>(out + (size_t)(row0 + r) * 64)[lane] =
            make_float2(w0[r], w1[r]);
}

// ---------- launch ----------
extern "C" void kernel_launch(void* const* d_in, const int* in_sizes, int n_in,
                              void* d_out, int out_size) {
    const float* x     = (const float*)d_in[0];
    const float* W1    = (const float*)d_in[1];
    const float* b1    = (const float*)d_in[2];
    const float* W2    = (const float*)d_in[3];
    const float* b2    = (const float*)d_in[4];
    const float* W3    = (const float*)d_in[5];
    const float* b3    = (const float*)d_in[6];
    const float* sigma = (const float*)d_in[7];
    const float* gamma = (const float*)d_in[8];
    float* out = (float*)d_out;

    int B = in_sizes[0] / 128;  // x is [B, 128]

    int mlp_blocks = (B + 7) / 8;
    prep_kernel<<<mlp_blocks + 1, 256>>>(x, W1, b1, W2, b2, W3, b3, sigma,
                                         out + (size_t)B * 64, B);
    int warps = (B + NROW - 1) / NROW;
    fista_kernel<<<(warps + 3) / 4, 128>>>(sigma, gamma, out, B);
}

// round 11
// speedup vs baseline: 3.6589x; 1.1971x over previous
#include <cuda_runtime.h>
#include <cstdint>

#define FULL 0xffffffffu
typedef unsigned long long ull;

__device__ float g_step;

// ---------- f32x2 packed helpers (sm_103a) ----------
static __device__ __forceinline__ ull pack2(float lo, float hi) {
    ull r;
    asm("mov.b64 %0, {%1, %2};" : "=l"(r) : "f"(lo), "f"(hi));
    return r;
}
static __device__ __forceinline__ void unpack2(ull v, float& lo, float& hi) {
    asm("mov.b64 {%0, %1}, %2;" : "=f"(lo), "=f"(hi) : "l"(v));
}
static __device__ __forceinline__ ull fma2(ull a, ull b, ull c) {
    ull d;
    asm("fma.rn.f32x2 %0, %1, %2, %3;" : "=l"(d) : "l"(a), "l"(b), "l"(c));
    return d;
}
static __device__ __forceinline__ ull add2(ull a, ull b) {
    ull d;
    asm("add.rn.f32x2 %0, %1, %2;" : "=l"(d) : "l"(a), "l"(b));
    return d;
}
static __device__ __forceinline__ float hadd2(ull v) {
    float lo, hi;
    unpack2(v, lo, hi);
    return lo + hi;
}

// ---------- power iteration body (1 warp): step = 1/(1.02 * lambda_max) ----------
static __device__ void power_body(const float* __restrict__ sigma, int lane) {
    __shared__ float vbuf[2][64];
    int c0 = 2 * lane;

    ull sp0[32], sp1[32];
    {
        const ull* r0 = reinterpret_cast<const ull*>(sigma + (size_t)c0 * 64);
        const ull* r1 = reinterpret_cast<const ull*>(sigma + (size_t)(c0 + 1) * 64);
        #pragma unroll
        for (int k = 0; k < 32; ++k) { sp0[k] = r0[k]; sp1[k] = r1[k]; }
    }

    float v0 = 0.125f, v1 = 0.125f;

    #pragma unroll 1
    for (int it = 0; it < 161; ++it) {
        int bsel = it & 1;
        *reinterpret_cast<ull*>(&vbuf[bsel][c0]) = pack2(v0, v1);
        __syncwarp();
        const ulonglong2* Y = reinterpret_cast<const ulonglong2*>(&vbuf[bsel][0]);
        ull a0 = 0ull, a1 = 0ull, b0 = 0ull, b1 = 0ull;
        #pragma unroll
        for (int q = 0; q < 16; ++q) {
            ulonglong2 yq = Y[q];
            a0 = fma2(sp0[2 * q],     yq.x, a0);
            a1 = fma2(sp1[2 * q],     yq.x, a1);
            b0 = fma2(sp0[2 * q + 1], yq.y, b0);
            b1 = fma2(sp1[2 * q + 1], yq.y, b1);
        }
        float u0 = hadd2(add2(a0, b0));
        float u1 = hadd2(add2(a1, b1));
        if (it == 160) {
            // Scale-invariant Rayleigh quotient: lam = (v.Sv)/(v.v)
            float num = u0 * v0 + u1 * v1;
            float den = v0 * v0 + v1 * v1;
            #pragma unroll
            for (int off = 16; off; off >>= 1) {
                num += __shfl_xor_sync(FULL, num, off);
                den += __shfl_xor_sync(FULL, den, off);
            }
            // 2% deflation guards a slight lambda underestimate; the converged
            // FISTA fixed point is step-independent.
            if (lane == 0) g_step = den / (1.02f * num);
            return;
        }
        if ((it & 15) == 15) {  // normalize every 16 iters (4^16 growth fits fp32)
            float nn = u0 * u0 + u1 * u1;
            #pragma unroll
            for (int off = 16; off; off >>= 1) nn += __shfl_xor_sync(FULL, nn, off);
            float inv = rsqrtf(nn);
            v0 = u0 * inv; v1 = u1 * inv;
        } else {
            v0 = u0; v1 = u1;
        }
    }
}

// ---------- Kernel 1: MLP -> mu, power iteration riding in the last block ----------
__global__ void __launch_bounds__(256) prep_kernel(
    const float* __restrict__ x,
    const float* __restrict__ W1, const float* __restrict__ b1,
    const float* __restrict__ W2, const float* __restrict__ b2,
    const float* __restrict__ W3, const float* __restrict__ b3,
    const float* __restrict__ sigma,
    float* __restrict__ mu_out, int B)
{
    if (blockIdx.x == gridDim.x - 1) {
        if (threadIdx.x < 32) power_body(sigma, threadIdx.x);
        return;
    }

    __shared__ float W1s[128 * 32];
    __shared__ float W2s[32 * 16];
    __shared__ float W3s[16 * 64];
    __shared__ float b1s[32], b2s[16], b3s[64];

    int tid = threadIdx.x;
    for (int i = tid; i < 4096; i += 256) W1s[i] = W1[i];
    for (int i = tid; i < 512;  i += 256) W2s[i] = W2[i];
    for (int i = tid; i < 1024; i += 256) W3s[i] = W3[i];
    if (tid < 32) b1s[tid] = b1[tid];
    if (tid < 16) b2s[tid] = b2[tid];
    if (tid < 64) b3s[tid] = b3[tid];
    __syncthreads();

    int lane = tid & 31;
    int row  = blockIdx.x * 8 + (tid >> 5);
    if (row >= B) return;

    float4 xv = reinterpret_cast<const float4*>(x + (size_t)row * 128)[lane];

    float h1 = b1s[lane];
    #pragma unroll
    for (int k = 0; k < 32; ++k) {
        float a0 = __shfl_sync(FULL, xv.x, k);
        float a1 = __shfl_sync(FULL, xv.y, k);
        float a2 = __shfl_sync(FULL, xv.z, k);
        float a3 = __shfl_sync(FULL, xv.w, k);
        int d = 4 * k;
        h1 = fmaf(a0, W1s[(d + 0) * 32 + lane], h1);
        h1 = fmaf(a1, W1s[(d + 1) * 32 + lane], h1);
        h1 = fmaf(a2, W1s[(d + 2) * 32 + lane], h1);
        h1 = fmaf(a3, W1s[(d + 3) * 32 + lane], h1);
    }
    h1 = fmaxf(h1, 0.f);

    int j = lane & 15;
    float h2 = b2s[j];
    #pragma unroll
    for (int k = 0; k < 32; ++k) {
        float hk = __shfl_sync(FULL, h1, k);
        h2 = fmaf(hk, W2s[k * 16 + j], h2);
    }
    h2 = fmaxf(h2, 0.f);

    float m0 = b3s[2 * lane];
    float m1 = b3s[2 * lane + 1];
    #pragma unroll
    for (int k = 0; k < 16; ++k) {
        float hk = __shfl_sync(FULL, h2, k);
        m0 = fmaf(hk, W3s[k * 64 + 2 * lane],     m0);
        m1 = fmaf(hk, W3s[k * 64 + 2 * lane + 1], m1);
    }
    reinterpret_cast<float2*>(mu_out + (size_t)row * 64)[lane] = make_float2(m0, m1);
}

// ---------- Kernel 2: FISTA, 2 rows/warp, 3 blocks/SM (12 warps) ----------
#define FIX    2097152.0f          /* 2^21 fixed-point scale for REDUX float sums */
#define INVFIX (1.0f / 2097152.0f)
#define NROW 2
#define RESTART 50                 /* momentum reset period (kills FISTA ripple) */

__global__ void __launch_bounds__(128, 3) fista_kernel(
    const float* __restrict__ sigma,
    const float* __restrict__ gamma,
    float* __restrict__ out, int B)
{
    __shared__ float ybuf[2][4][NROW][64];   // [buf][warp][row][64] = 4KB

    int warp = threadIdx.x >> 5;
    int lane = threadIdx.x & 31;
    int gw   = blockIdx.x * 4 + warp;        // warp task id (NROW rows each)
    int row0 = NROW * gw;
    if (row0 >= B) return;

    const float gm   = __ldg(gamma);
    const float step = g_step;
    const int   c0   = 2 * lane;             // lane owns columns 2l, 2l+1

    ull sp0[32], sp1[32];
    {
        const ull* r0 = reinterpret_cast<const ull*>(sigma + (size_t)c0 * 64);
        const ull* r1 = reinterpret_cast<const ull*>(sigma + (size_t)(c0 + 1) * 64);
        #pragma unroll
        for (int k = 0; k < 32; ++k) { sp0[k] = r0[k]; sp1[k] = r1[k]; }
    }

    // p = -gamma * mu  (mu at out[B*64 + ...], written by prep_kernel)
    float p0[NROW], p1[NROW];
    #pragma unroll
    for (int r = 0; r < NROW; ++r) {
        const float2 m = reinterpret_cast<const float2*>(
            out + (size_t)B * 64 + (size_t)(row0 + r) * 64)[lane];
        p0[r] = -gm * m.x; p1[r] = -gm * m.y;
    }

    float w0[NROW], w1[NROW], y0[NROW], y1[NROW], th[NROW];
    #pragma unroll
    for (int r = 0; r < NROW; ++r) {
        w0[r] = 1.f / 64.f; w1[r] = 1.f / 64.f;
        y0[r] = w0[r];      y1[r] = w1[r];
        th[r] = -1e30f;     // warm-start theta; -inf => cold start on iter 0
    }
    float t = 1.f;
    int cc = 0, rsc = 0;

    #pragma unroll 1
    for (int it = 0; it < 200; ++it) {
        int bsel = it & 1;
        #pragma unroll
        for (int r = 0; r < NROW; ++r)
            *reinterpret_cast<ull*>(&ybuf[bsel][warp][r][c0]) = pack2(y0[r], y1[r]);
        __syncwarp();

        // grad = y @ Sigma + p  (Sigma symmetric; broadcast LDS.128 reads)
        ull a0[NROW], a1[NROW];
        #pragma unroll
        for (int r = 0; r < NROW; ++r) { a0[r] = 0ull; a1[r] = 0ull; }
        #pragma unroll
        for (int q = 0; q < 16; ++q) {
            #pragma unroll
            for (int r = 0; r < NROW; ++r) {
                ulonglong2 yq = reinterpret_cast<const ulonglong2*>(&ybuf[bsel][warp][r][0])[q];
                a0[r] = fma2(sp0[2 * q],     yq.x, a0[r]);
                a1[r] = fma2(sp1[2 * q],     yq.x, a1[r]);
                a0[r] = fma2(sp0[2 * q + 1], yq.y, a0[r]);
                a1[r] = fma2(sp1[2 * q + 1], yq.y, a1[r]);
            }
        }

        float v0[NROW], v1[NROW];
        #pragma unroll
        for (int r = 0; r < NROW; ++r) {
            float gr0 = hadd2(a0[r]) + p0[r];
            float gr1 = hadd2(a1[r]) + p1[r];
            v0[r] = fmaf(-step, gr0, y0[r]);
            v1[r] = fmaf(-step, gr1, y1[r]);
        }

        // Simplex projection: warm-started Newton on g(th)=sum(max(v-th,0))-1.
        // First step lands <= th*, then monotone increase, exact finite stop.
        // Sum via 2^21 fixed-point REDUX (theta err ~1e-6 << 1e-3 budget);
        // active-set count via ballot+popc (VOTE pipe, off the REDUX chain).
        int kc[NROW];
        #pragma unroll
        for (int r = 0; r < NROW; ++r) kc[r] = -1;

        #pragma unroll 1
        for (int pass = 0; pass < 64; ++pass) {
            int s[NROW], c[NROW];
            #pragma unroll
            for (int r = 0; r < NROW; ++r) {
                bool g0 = v0[r] > th[r], g1 = v1[r] > th[r];
                float ps = (g0 ? v0[r] : 0.f) + (g1 ? v1[r] : 0.f);
                s[r] = __reduce_add_sync(FULL, __float2int_rn(ps * FIX));
                c[r] = __popc(__ballot_sync(FULL, g0)) + __popc(__ballot_sync(FULL, g1));
            }
            bool done = true;
            #pragma unroll
            for (int r = 0; r < NROW; ++r) {
                done &= (c[r] == kc[r]);
                kc[r] = c[r];
                // c==0 only possible on pass 0 (warm theta too high): cold restart
                th[r] = (c[r] > 0)
                    ? __fdividef((float)s[r] * INVFIX - 1.f, (float)c[r])
                    : -1e30f;
            }
            if (done) break;  // same active set twice => consistent fixed point
        }

        float mxchg = 0.f;
        float wn0[NROW], wn1[NROW];
        #pragma unroll
        for (int r = 0; r < NROW; ++r) {
            wn0[r] = fmaxf(v0[r] - th[r], 0.f);
            wn1[r] = fmaxf(v1[r] - th[r], 0.f);
            mxchg = fmaxf(mxchg, fmaxf(fabsf(wn0[r] - w0[r]), fabsf(wn1[r] - w1[r])));
        }

        // Periodic restart: dump momentum so w converges monotonically
        // (same fixed point; lets the early exit below actually fire).
        bool restart = (++rsc == RESTART);
        if (restart) rsc = 0;
        float tn = restart ? 1.f : 0.5f * (1.f + sqrtf(fmaf(4.f * t, t, 1.f)));
        float cf = restart ? 0.f : __fdividef(t - 1.f, tn);
        #pragma unroll
        for (int r = 0; r < NROW; ++r) {
            y0[r] = fmaf(cf, wn0[r] - w0[r], wn0[r]);
            y1[r] = fmaf(cf, wn1[r] - w1[r], wn1[r]);
            w0[r] = wn0[r]; w1[r] = wn1[r];
        }
        t = tn;

        // Early exit: w frozen (<1e-7) across whole warp for 2 consecutive iters.
        if (__all_sync(FULL, mxchg < 1e-7f)) {
            if (++cc >= 2) break;
        } else {
            cc = 0;
        }
    }

    #pragma unroll
    for (int r = 0; r < NROW; ++r)
        reinterpret_cast<float2*>(out + (size_t)(row0 + r) * 64)[lane] =
            make_float2(w0[r], w1[r]);
}

// ---------- launch ----------
extern "C" void kernel_launch(void* const* d_in, const int* in_sizes, int n_in,
                              void* d_out, int out_size) {
    const float* x     = (const float*)d_in[0];
    const float* W1    = (const float*)d_in[1];
    const float* b1    = (const float*)d_in[2];
    const float* W2    = (const float*)d_in[3];
    const float* b2    = (const float*)d_in[4];
    const float* W3    = (const float*)d_in[5];
    const float* b3    = (const float*)d_in[6];
    const float* sigma = (const float*)d_in[7];
    const float* gamma = (const float*)d_in[8];
    float* out = (float*)d_out;

    int B = in_sizes[0] / 128;  // x is [B, 128]

    int mlp_blocks = (B + 7) / 8;
    prep_kernel<<<mlp_blocks + 1, 256>>>(x, W1, b1, W2, b2, W3, b3, sigma,
                                         out + (size_t)B * 64, B);
    int warps = (B + NROW - 1) / NROW;
    fista_kernel<<<(warps + 3) / 4, 128>>>(sigma, gamma, out, B);
}